// round 5
// baseline (speedup 1.0000x reference)
#include <cuda_runtime.h>
#include <cuda_bf16.h>
#include <cstdint>

#define DD 512
#define MAXN 200000
#define TAU_INV 2.0f
#define EPS 1e-8f

// ---------------- device scratch (no allocations allowed) ----------------
__device__ __align__(256) __nv_bfloat16 g_zbf[(size_t)MAXN * DD];   // z in bf16
__device__ __align__(256) __nv_bfloat16 g_wbf[DD * DD];             // W in bf16
__device__ float g_s[MAXN];                          // row sumsq of z (fp32)
__device__ float g_d2[MAXN];
__device__ float g_colsum[DD];
__device__ float g_c0[DD];                           // init centroid
__device__ float g_cp[DD];                           // unnormalized softmax centroid
__device__ float g_c[DD];                            // normalized centroid
__device__ float g_cc;                               // ||c0||^2
__device__ float g_Z;                                // softmax partition
__device__ float g_cnorm;                            // max(||c||, eps)
__device__ int   g_d2min_bits;

// ---------------- helpers ----------------
__device__ __forceinline__ uint32_t smem_u32(const void* p) {
    return (uint32_t)__cvta_generic_to_shared(p);
}
__device__ __forceinline__ void ldmx4(uint32_t* r, uint32_t addr) {
    asm volatile("ldmatrix.sync.aligned.m8n8.x4.shared.b16 {%0,%1,%2,%3}, [%4];"
                 : "=r"(r[0]), "=r"(r[1]), "=r"(r[2]), "=r"(r[3]) : "r"(addr));
}
__device__ __forceinline__ void mma16816(float* c, const uint32_t* a, const uint32_t* b) {
    asm volatile("mma.sync.aligned.m16n8k16.row.col.f32.bf16.bf16.f32 "
                 "{%0,%1,%2,%3}, {%4,%5,%6,%7}, {%8,%9}, {%0,%1,%2,%3};"
                 : "+f"(c[0]), "+f"(c[1]), "+f"(c[2]), "+f"(c[3])
                 : "r"(a[0]), "r"(a[1]), "r"(a[2]), "r"(a[3]), "r"(b[0]), "r"(b[1]));
}
__device__ __forceinline__ void cp_async16(uint32_t sdst, const void* gsrc) {
    asm volatile("cp.async.cg.shared.global [%0], [%1], 16;"
                 :: "r"(sdst), "l"(gsrc) : "memory");
}
__device__ __forceinline__ void cp_commit() {
    asm volatile("cp.async.commit_group;" ::: "memory");
}
__device__ __forceinline__ void cp_wait2() {
    asm volatile("cp.async.wait_group 2;" ::: "memory");
}

// ================= k0: init scratch + W -> bf16 =================
__global__ void k0_init(const float* __restrict__ W) {
    int i = blockIdx.x * blockDim.x + threadIdx.x;
    int stride = gridDim.x * blockDim.x;
    for (int j = i; j < DD * DD; j += stride) g_wbf[j] = __float2bfloat16(W[j]);
    if (i < DD) { g_colsum[i] = 0.f; g_cp[i] = 0.f; }
    if (i == 0) { g_Z = 0.f; g_d2min_bits = 0x7f7fffff; }
}

// ================= k1: colsums + row sumsq + z->bf16 (streaming) =========
__global__ void k1_pass1(const float* __restrict__ z, int N) {
    __shared__ float scol[DD];
    const int tid = threadIdx.x, wid = tid >> 5, lane = tid & 31;
    for (int i = tid; i < DD; i += blockDim.x) scol[i] = 0.f;
    __syncthreads();
    const int gw = blockIdx.x * (blockDim.x >> 5) + wid;
    const int nw = gridDim.x * (blockDim.x >> 5);
    float cs[16];
#pragma unroll
    for (int i = 0; i < 16; i++) cs[i] = 0.f;
    for (int row = gw; row < N; row += nw) {
        const float4* zr = (const float4*)(z + (size_t)row * DD);
        float ssq = 0.f;
#pragma unroll
        for (int c = 0; c < 4; c++) {
            float4 v = __ldcs(zr + c * 32 + lane);
            ssq += v.x * v.x + v.y * v.y + v.z * v.z + v.w * v.w;
            cs[c * 4 + 0] += v.x; cs[c * 4 + 1] += v.y;
            cs[c * 4 + 2] += v.z; cs[c * 4 + 3] += v.w;
            __nv_bfloat162 b0 = __floats2bfloat162_rn(v.x, v.y);
            __nv_bfloat162 b1 = __floats2bfloat162_rn(v.z, v.w);
            float2 u;
            u.x = __uint_as_float(*reinterpret_cast<uint32_t*>(&b0));
            u.y = __uint_as_float(*reinterpret_cast<uint32_t*>(&b1));
            __stcs((float2*)(g_zbf + (size_t)row * DD + c * 128 + lane * 4), u);
        }
#pragma unroll
        for (int o = 16; o > 0; o >>= 1) ssq += __shfl_xor_sync(0xffffffffu, ssq, o);
        if (lane == 0) g_s[row] = ssq;
    }
#pragma unroll
    for (int c = 0; c < 4; c++)
#pragma unroll
        for (int e = 0; e < 4; e++)
            atomicAdd(&scol[c * 128 + lane * 4 + e], cs[c * 4 + e]);
    __syncthreads();
    for (int i = tid; i < DD; i += blockDim.x) atomicAdd(&g_colsum[i], scol[i]);
}

// ================= k2: c0 = colsum/N, cc = ||c0||^2 =================
__global__ void k2_c0(int N) {
    __shared__ float red[16];
    const int tid = threadIdx.x; // 512
    float c0 = g_colsum[tid] / (float)N;
    g_c0[tid] = c0;
    float sq = c0 * c0;
#pragma unroll
    for (int o = 16; o > 0; o >>= 1) sq += __shfl_xor_sync(0xffffffffu, sq, o);
    if ((tid & 31) == 0) red[tid >> 5] = sq;
    __syncthreads();
    if (tid < 16) {
        float s = red[tid];
#pragma unroll
        for (int o = 8; o > 0; o >>= 1) s += __shfl_xor_sync(0xffffu, s, o);
        if (tid == 0) g_cc = s;
    }
}

// ================= k3: d2 = s - 2 h.c0 + cc (bf16 h), block-min =================
__global__ void k3_d2(int N) {
    __shared__ __align__(16) float c0s[DD];
    __shared__ int smin;
    const int tid = threadIdx.x, wid = tid >> 5, lane = tid & 31;
    for (int i = tid; i < DD; i += blockDim.x) c0s[i] = g_c0[i];
    if (tid == 0) smin = 0x7f7fffff;
    __syncthreads();
    const float cc = g_cc;
    const int gw = blockIdx.x * (blockDim.x >> 5) + wid;
    const int nw = gridDim.x * (blockDim.x >> 5);
    for (int r4 = gw * 4; r4 < N; r4 += nw * 4) {
        float t[4] = {0.f, 0.f, 0.f, 0.f};
        int nr = (N - r4 < 4) ? (N - r4) : 4;
#pragma unroll
        for (int q = 0; q < 4; q++) {
            int row = r4 + ((q < nr) ? q : 0);
#pragma unroll
            for (int c = 0; c < 2; c++) {
                uint4 u = __ldcs((const uint4*)(g_zbf + (size_t)row * DD + c * 256 + lane * 8));
                const __nv_bfloat162* p = (const __nv_bfloat162*)&u;
                float4 cv0 = ((const float4*)c0s)[c * 64 + lane * 2];
                float4 cv1 = ((const float4*)c0s)[c * 64 + lane * 2 + 1];
                float2 f0 = __bfloat1622float2(p[0]);
                float2 f1 = __bfloat1622float2(p[1]);
                float2 f2 = __bfloat1622float2(p[2]);
                float2 f3 = __bfloat1622float2(p[3]);
                t[q] += f0.x * cv0.x + f0.y * cv0.y + f1.x * cv0.z + f1.y * cv0.w
                      + f2.x * cv1.x + f2.y * cv1.y + f3.x * cv1.z + f3.y * cv1.w;
            }
        }
#pragma unroll
        for (int q = 0; q < 4; q++)
#pragma unroll
            for (int o = 16; o > 0; o >>= 1)
                t[q] += __shfl_xor_sync(0xffffffffu, t[q], o);
        if (lane == 0) {
            int lmin = 0x7f7fffff;
#pragma unroll
            for (int q = 0; q < 4; q++) {
                if (q < nr) {
                    float d2 = g_s[r4 + q] - 2.f * t[q] + cc;
                    g_d2[r4 + q] = d2;
                    int bits = __float_as_int(d2);
                    if (bits < lmin) lmin = bits;
                }
            }
            atomicMin(&smin, lmin);
        }
    }
    __syncthreads();
    if (tid == 0) atomicMin(&g_d2min_bits, smin);
}

// ================= k45: Z + unnormalized centroid c' (uniform trip count) ====
__global__ void k45_Zc(const float* __restrict__ z, int N) {
    __shared__ float red[8];
    const int tid = threadIdx.x, lane = tid & 31;
    const float d2min = __int_as_float(g_d2min_bits);
    const int gidx = blockIdx.x * blockDim.x + tid;
    const int stride = gridDim.x * blockDim.x;
    const int numIter = (N + stride - 1) / stride;   // identical for all threads
    float zpart = 0.f;
    for (int i = 0; i < numIter; i++) {
        int r = gidx + i * stride;
        float e = 0.f;
        if (r < N) e = __expf((d2min - g_d2[r]) * TAU_INV);
        zpart += e;
        unsigned mask = __ballot_sync(0xffffffffu, e > 1e-13f);
        while (mask) {
            int src = __ffs(mask) - 1;
            mask &= mask - 1;
            int rb = __shfl_sync(0xffffffffu, r, src);
            float eb = __shfl_sync(0xffffffffu, e, src);
            const float* zr = z + (size_t)rb * DD;
#pragma unroll
            for (int c = 0; c < 16; c++)
                atomicAdd(&g_cp[c * 32 + lane], eb * zr[c * 32 + lane]);
        }
    }
#pragma unroll
    for (int o = 16; o > 0; o >>= 1) zpart += __shfl_xor_sync(0xffffffffu, zpart, o);
    if (lane == 0) red[tid >> 5] = zpart;
    __syncthreads();
    if (tid < 8) {
        float t = red[tid];
#pragma unroll
        for (int o = 4; o > 0; o >>= 1) t += __shfl_xor_sync(0xffu, t, o);
        if (tid == 0) atomicAdd(&g_Z, t);
    }
}

// ================= k7: c = c'/Z, cnorm =================
__global__ void k7_norm() {
    __shared__ float red[16];
    const int tid = threadIdx.x; // 512
    const float invZ = 1.f / g_Z;
    float cv = g_cp[tid] * invZ;
    g_c[tid] = cv;
    float pc = cv * cv;
#pragma unroll
    for (int o = 16; o > 0; o >>= 1) pc += __shfl_xor_sync(0xffffffffu, pc, o);
    if ((tid & 31) == 0) red[tid >> 5] = pc;
    __syncthreads();
    if (tid < 16) {
        float sc = red[tid];
#pragma unroll
        for (int o = 8; o > 0; o >>= 1) sc += __shfl_xor_sync(0xffffu, sc, o);
        if (tid == 0) g_cnorm = fmaxf(sqrtf(sc), EPS);
    }
}

// ================= k8: mma.sync GEMM, deep cp.async pipeline =================
// Warp tile m64 x j32 (2 m-groups x 4 j-groups), j-chunk 128, k-quantum 64.
// SMEM (bytes):
//   A    : [0, 131072)            128 rows x 512 bf16, pitch 1024, XOR swizzle
//   B    : [131072, +4x16384)     4 bufs, 128 j x 64 k bf16, pitch 128
//   c    : [196608, 198656)       512 f32
//   b    : [198656, 200704)       512 f32
//   nsq  : [200704, 201216)       128 f32
//   cos  : [201216, 201728)       128 f32
#define K8_A    0
#define K8_B    131072
#define K8_BB   16384
#define K8_C    196608
#define K8_BV   198656
#define K8_NSQ  200704
#define K8_COS  201216
#define K8_SMEM 201728

__global__ void __launch_bounds__(256, 1)
k8_gemm(const float* __restrict__ b_in, float* __restrict__ out, int N) {
    extern __shared__ char smem[];
    const uint32_t sbase = smem_u32(smem);
    const int tid = threadIdx.x, warp = tid >> 5, lane = tid & 31;
    const int m0 = blockIdx.x * 128;

    float* sc  = (float*)(smem + K8_C);
    float* sbv = (float*)(smem + K8_BV);
    float* snq = (float*)(smem + K8_NSQ);
    float* sco = (float*)(smem + K8_COS);

    for (int i = tid; i < DD; i += 256) { sc[i] = g_c[i]; sbv[i] = b_in[i]; }
    if (tid < 128) { snq[tid] = 0.f; sco[tid] = 0.f; }

    // ---- group 0: A tile via cp.async (128 rows x 512 bf16 = 128 KB) ----
#pragma unroll
    for (int it = 0; it < 32; it++) {
        int idx = it * 256 + tid;
        int r = idx >> 6, ci = idx & 63;
        int grow = m0 + r; if (grow > N - 1) grow = N - 1;
        cp_async16(sbase + K8_A + r * 1024 + ((ci ^ (r & 7)) << 4),
                   g_zbf + (size_t)grow * DD + ci * 8);
    }
    cp_commit();

    // ---- groups 1..3: B chunks h=0,1,2 (each 128 j x 64 k = 16 KB) ----
#pragma unroll 1
    for (int h = 0; h < 3; h++) {
        const uint32_t bbuf = sbase + K8_B + (h & 3) * K8_BB;
        const int jc = h >> 3, kq = h & 7;
#pragma unroll
        for (int it = 0; it < 4; it++) {
            int idx = it * 256 + tid;
            int j = idx >> 3, ci = idx & 7;
            cp_async16(bbuf + j * 128 + ((ci ^ (j & 7)) << 4),
                       g_wbf + (size_t)(jc * 128 + j) * DD + kq * 64 + ci * 8);
        }
        cp_commit();
    }

    // ---- warp coords: mg = warp>>2 (m64), jg = warp&3 (j32 of j128 chunk) --
    const int mg = warp >> 2, jg = warp & 3;
    const int mbase = mg * 64;
    const uint32_t swa = lane & 7;
    const uint32_t a0base = sbase + K8_A + (uint32_t)(mbase + (lane & 15)) * 1024;
    const int jrow = (lane & 7) + ((lane >> 4) << 3);
    const uint32_t brow_off = (uint32_t)(jg * 32 + jrow) * 128;
    const uint32_t ciBofs = (lane >> 3) & 1;
    const uint32_t ciAofs = lane >> 4;

    float acc[16][4];
#pragma unroll
    for (int t = 0; t < 16; t++)
#pragma unroll
        for (int e = 0; e < 4; e++) acc[t][e] = 0.f;
    float nsq[4][2] = {{0.f,0.f},{0.f,0.f},{0.f,0.f},{0.f,0.f}};
    float cqs[4][2] = {{0.f,0.f},{0.f,0.f},{0.f,0.f},{0.f,0.f}};

    for (int h = 0; h < 32; h++) {           // jc = h>>3 (j128), kq = h&7 (k64)
        const int jc = h >> 3, kq = h & 7;
        cp_wait2();
        __syncthreads();
        const uint32_t b0base = sbase + K8_B + (h & 3) * K8_BB + brow_off;

#pragma unroll
        for (int ktl = 0; ktl < 4; ktl++) {
            uint32_t a[4][4], b0[4], b1[4];
            uint32_t ciA = (uint32_t)(kq * 4 + ktl) * 2 + ciAofs;
            uint32_t adr = a0base + ((ciA ^ swa) << 4);
            ldmx4(a[0], adr);
            ldmx4(a[1], adr + 16 * 1024);
            ldmx4(a[2], adr + 32 * 1024);
            ldmx4(a[3], adr + 48 * 1024);
            uint32_t ciB = (uint32_t)ktl * 2 + ciBofs;
            uint32_t bdr = b0base + ((ciB ^ swa) << 4);
            ldmx4(b0, bdr);
            ldmx4(b1, bdr + 16 * 128);
#pragma unroll
            for (int mt = 0; mt < 4; mt++) {
                mma16816(acc[mt * 4 + 0], a[mt], b0 + 0);
                mma16816(acc[mt * 4 + 1], a[mt], b0 + 2);
                mma16816(acc[mt * 4 + 2], a[mt], b1 + 0);
                mma16816(acc[mt * 4 + 3], a[mt], b1 + 2);
            }
        }

        if (kq == 7) {
            // j128 chunk complete: fold (acc + b)^2 and (acc + b)*c, reset acc
#pragma unroll
            for (int mt = 0; mt < 4; mt++)
#pragma unroll
                for (int nt = 0; nt < 4; nt++) {
                    int jglob = jc * 128 + jg * 32 + nt * 8 + (lane & 3) * 2;
                    float bx = sbv[jglob], by = sbv[jglob + 1];
                    float cx = sc[jglob],  cy = sc[jglob + 1];
                    float* a = acc[mt * 4 + nt];
                    float v0 = a[0] + bx, v1 = a[1] + by;
                    float v2 = a[2] + bx, v3 = a[3] + by;
                    nsq[mt][0] += v0 * v0 + v1 * v1;
                    nsq[mt][1] += v2 * v2 + v3 * v3;
                    cqs[mt][0] += v0 * cx + v1 * cy;
                    cqs[mt][1] += v2 * cx + v3 * cy;
                    a[0] = 0.f; a[1] = 0.f; a[2] = 0.f; a[3] = 0.f;
                }
        }
        // refill buffer (h+3)%4 for iteration h+3 (buffer freed at iter h-1)
        if (h + 3 < 32) {
            const int h2 = h + 3;
            const uint32_t bbuf = sbase + K8_B + (h2 & 3) * K8_BB;
            const int jc2 = h2 >> 3, kq2 = h2 & 7;
#pragma unroll
            for (int it = 0; it < 4; it++) {
                int idx = it * 256 + tid;
                int j = idx >> 3, ci = idx & 7;
                cp_async16(bbuf + j * 128 + ((ci ^ (j & 7)) << 4),
                           g_wbf + (size_t)(jc2 * 128 + j) * DD + kq2 * 64 + ci * 8);
            }
        }
        cp_commit();
    }

    // ---- merge lane partials: quad lanes share a row ----
#pragma unroll
    for (int mt = 0; mt < 4; mt++)
#pragma unroll
        for (int hh = 0; hh < 2; hh++) {
            float vn = nsq[mt][hh], vc = cqs[mt][hh];
            vn += __shfl_xor_sync(0xffffffffu, vn, 1);
            vn += __shfl_xor_sync(0xffffffffu, vn, 2);
            vc += __shfl_xor_sync(0xffffffffu, vc, 1);
            vc += __shfl_xor_sync(0xffffffffu, vc, 2);
            if ((lane & 3) == 0) {
                int r = mbase + mt * 16 + hh * 8 + (lane >> 2);
                atomicAdd(&snq[r], vn);
                atomicAdd(&sco[r], vc);
            }
        }
    __syncthreads();

    if (tid < 128 && m0 + tid < N) {
        float nx = fmaxf(sqrtf(snq[tid]), EPS);
        out[m0 + tid] = 1.0f - sco[tid] / (nx * g_cnorm);
    }
}

// ================= launch =================
extern "C" void kernel_launch(void* const* d_in, const int* in_sizes, int n_in,
                              void* d_out, int out_size) {
    const float* z = (const float*)d_in[0];
    const float* W = (const float*)d_in[1];
    const float* b = (const float*)d_in[2];
    float* out = (float*)d_out;
    const int N = in_sizes[0] / DD;

    k0_init<<<1024, 256>>>(W);
    k1_pass1<<<1184, 256>>>(z, N);
    k2_c0<<<1, 512>>>(N);
    k3_d2<<<1184, 256>>>(N);
    k45_Zc<<<592, 256>>>(z, N);
    k7_norm<<<1, 512>>>();
    cudaFuncSetAttribute(k8_gemm, cudaFuncAttributeMaxDynamicSharedMemorySize, K8_SMEM);
    k8_gemm<<<(N + 127) / 128, 256, K8_SMEM>>>(b, out, N);
}